// round 1
// baseline (speedup 1.0000x reference)
#include <cuda_runtime.h>
#include <math.h>

#define BATCH 4
#define CHN 64
#define HW 65536        // 256*256
#define NDS 4096        // 64*64 downsampled pixels
#define THITA_F 1.0e-4f

// ---------------- scratch (device globals; no allocations allowed) ----------
__device__ float g_efd[BATCH * CHN * NDS];   // ef after 2nd conv, downsampled
__device__ float g_q[BATCH * CHN * NDS];
__device__ float g_k[BATCH * CHN * NDS];
__device__ float g_v[BATCH * CHN * NDS];
__device__ float g_O[BATCH * CHN * NDS];     // attention output (pre-upsample)

// ============================================================================
// K1: x = relu(xw0 @ concat(x1,x2) + xb0) at full resolution.
// Writes directly into d_out first half (the attention term is added later).
// Per block: 128 pixels, 1 pixel/thread, 64 accumulators, weights in smem.
// ============================================================================
__global__ __launch_bounds__(128) void conv0_kernel(
    const float* __restrict__ x1, const float* __restrict__ x2,
    const float* __restrict__ w,  const float* __restrict__ bias,
    float* __restrict__ out)
{
    __shared__ float ws[64 * 192];   // ws[o*192 + c], 48 KB exactly
    int tid = threadIdx.x;
    #pragma unroll
    for (int i = 0; i < 96; i++) ws[i * 128 + tid] = w[i * 128 + tid];
    __syncthreads();

    int b = blockIdx.y;
    int p = (blockIdx.x << 7) + tid;
    const float* px1 = x1 + (size_t)b * 128 * HW + p;
    const float* px2 = x2 + (size_t)b * 64  * HW + p;

    float acc[64];
    #pragma unroll
    for (int o = 0; o < 64; o++) acc[o] = 0.0f;

    #pragma unroll 1
    for (int c = 0; c < 192; c += 4) {
        float v0, v1, v2, v3;
        if (c < 128) {
            const float* pp = px1 + (size_t)c * HW;
            v0 = pp[0]; v1 = pp[HW]; v2 = pp[2 * HW]; v3 = pp[3 * (size_t)HW];
        } else {
            const float* pp = px2 + (size_t)(c - 128) * HW;
            v0 = pp[0]; v1 = pp[HW]; v2 = pp[2 * HW]; v3 = pp[3 * (size_t)HW];
        }
        #pragma unroll
        for (int o = 0; o < 64; o++) {
            float4 w4 = *(const float4*)&ws[o * 192 + c];
            acc[o] = fmaf(w4.x, v0, acc[o]);
            acc[o] = fmaf(w4.y, v1, acc[o]);
            acc[o] = fmaf(w4.z, v2, acc[o]);
            acc[o] = fmaf(w4.w, v3, acc[o]);
        }
    }

    float* po = out + (size_t)b * 64 * HW + p;
    #pragma unroll
    for (int o = 0; o < 64; o++) {
        float r = acc[o] + __ldg(&bias[o]);
        po[(size_t)o * HW] = fmaxf(r, 0.0f);
    }
}

// ============================================================================
// K2: ef path, computed ONLY at downsampled pixels:
//   t  = relu(ew0 @ event_ds + eb0)
//   ef = relu(ew1 @ t        + eb1)   -> g_efd
// ============================================================================
__global__ __launch_bounds__(128) void ef_kernel(
    const float* __restrict__ event,
    const float* __restrict__ w0, const float* __restrict__ b0,
    const float* __restrict__ w1, const float* __restrict__ b1)
{
    __shared__ float ws[64 * 64];        // 16 KB
    __shared__ float ts[64][128];        // 32 KB
    int tid = threadIdx.x;
    int b   = blockIdx.y;
    int n   = (blockIdx.x << 7) + tid;               // downsampled linear idx
    int p   = ((n >> 6) << 10) + ((n & 63) << 2);    // full-res pixel (4y,4x)

    float acc[64];

    // phase 1: ew0 conv from gmem
    #pragma unroll
    for (int i = 0; i < 32; i++) ws[i * 128 + tid] = w0[i * 128 + tid];
    __syncthreads();
    #pragma unroll
    for (int o = 0; o < 64; o++) acc[o] = 0.0f;
    const float* pe = event + (size_t)b * 64 * HW + p;
    #pragma unroll 1
    for (int c = 0; c < 64; c += 4) {
        float v0 = pe[(size_t)c * HW];
        float v1 = pe[(size_t)(c + 1) * HW];
        float v2 = pe[(size_t)(c + 2) * HW];
        float v3 = pe[(size_t)(c + 3) * HW];
        #pragma unroll
        for (int o = 0; o < 64; o++) {
            float4 w4 = *(const float4*)&ws[o * 64 + c];
            acc[o] = fmaf(w4.x, v0, acc[o]);
            acc[o] = fmaf(w4.y, v1, acc[o]);
            acc[o] = fmaf(w4.z, v2, acc[o]);
            acc[o] = fmaf(w4.w, v3, acc[o]);
        }
    }
    #pragma unroll
    for (int o = 0; o < 64; o++) ts[o][tid] = fmaxf(acc[o] + __ldg(&b0[o]), 0.0f);
    __syncthreads();

    // phase 2: ew1 conv from smem
    #pragma unroll
    for (int i = 0; i < 32; i++) ws[i * 128 + tid] = w1[i * 128 + tid];
    __syncthreads();
    #pragma unroll
    for (int o = 0; o < 64; o++) acc[o] = 0.0f;
    #pragma unroll 1
    for (int c = 0; c < 64; c += 4) {
        float v0 = ts[c][tid], v1 = ts[c + 1][tid];
        float v2 = ts[c + 2][tid], v3 = ts[c + 3][tid];
        #pragma unroll
        for (int o = 0; o < 64; o++) {
            float4 w4 = *(const float4*)&ws[o * 64 + c];
            acc[o] = fmaf(w4.x, v0, acc[o]);
            acc[o] = fmaf(w4.y, v1, acc[o]);
            acc[o] = fmaf(w4.z, v2, acc[o]);
            acc[o] = fmaf(w4.w, v3, acc[o]);
        }
    }
    float* pd = g_efd + (b * 64) * NDS + n;
    #pragma unroll
    for (int o = 0; o < 64; o++) pd[o * NDS] = fmaxf(acc[o] + __ldg(&b1[o]), 0.0f);
}

// ============================================================================
// K3: t = relu(xw1 @ down4(x) + xb1); q = relu(qw@t+qb); v = relu(vw@t+vb);
//     k = relu(kw @ ef_d + kb). x read from d_out (written by K1).
// ============================================================================
__global__ __launch_bounds__(128) void qkv_kernel(
    const float* __restrict__ xsrc,
    const float* __restrict__ xw1, const float* __restrict__ xb1,
    const float* __restrict__ qw,  const float* __restrict__ qb,
    const float* __restrict__ kw,  const float* __restrict__ kb,
    const float* __restrict__ vw,  const float* __restrict__ vb)
{
    __shared__ float ws[64 * 64];
    __shared__ float ts[64][128];
    int tid = threadIdx.x;
    int b   = blockIdx.y;
    int n   = (blockIdx.x << 7) + tid;
    int p   = ((n >> 6) << 10) + ((n & 63) << 2);

    float acc[64];

    // phase 1: t = relu(xw1 @ x_ds + xb1) -> ts
    #pragma unroll
    for (int i = 0; i < 32; i++) ws[i * 128 + tid] = xw1[i * 128 + tid];
    __syncthreads();
    #pragma unroll
    for (int o = 0; o < 64; o++) acc[o] = 0.0f;
    const float* px = xsrc + (size_t)b * 64 * HW + p;
    #pragma unroll 1
    for (int c = 0; c < 64; c += 4) {
        float v0 = px[(size_t)c * HW];
        float v1 = px[(size_t)(c + 1) * HW];
        float v2 = px[(size_t)(c + 2) * HW];
        float v3 = px[(size_t)(c + 3) * HW];
        #pragma unroll
        for (int o = 0; o < 64; o++) {
            float4 w4 = *(const float4*)&ws[o * 64 + c];
            acc[o] = fmaf(w4.x, v0, acc[o]);
            acc[o] = fmaf(w4.y, v1, acc[o]);
            acc[o] = fmaf(w4.z, v2, acc[o]);
            acc[o] = fmaf(w4.w, v3, acc[o]);
        }
    }
    #pragma unroll
    for (int o = 0; o < 64; o++) ts[o][tid] = fmaxf(acc[o] + __ldg(&xb1[o]), 0.0f);
    __syncthreads();

    // q from ts
    #pragma unroll
    for (int i = 0; i < 32; i++) ws[i * 128 + tid] = qw[i * 128 + tid];
    __syncthreads();
    #pragma unroll
    for (int o = 0; o < 64; o++) acc[o] = 0.0f;
    #pragma unroll 1
    for (int c = 0; c < 64; c += 4) {
        float v0 = ts[c][tid], v1 = ts[c + 1][tid];
        float v2 = ts[c + 2][tid], v3 = ts[c + 3][tid];
        #pragma unroll
        for (int o = 0; o < 64; o++) {
            float4 w4 = *(const float4*)&ws[o * 64 + c];
            acc[o] = fmaf(w4.x, v0, acc[o]);
            acc[o] = fmaf(w4.y, v1, acc[o]);
            acc[o] = fmaf(w4.z, v2, acc[o]);
            acc[o] = fmaf(w4.w, v3, acc[o]);
        }
    }
    #pragma unroll
    for (int o = 0; o < 64; o++)
        g_q[(b * 64 + o) * NDS + n] = fmaxf(acc[o] + __ldg(&qb[o]), 0.0f);
    __syncthreads();

    // v from ts
    #pragma unroll
    for (int i = 0; i < 32; i++) ws[i * 128 + tid] = vw[i * 128 + tid];
    __syncthreads();
    #pragma unroll
    for (int o = 0; o < 64; o++) acc[o] = 0.0f;
    #pragma unroll 1
    for (int c = 0; c < 64; c += 4) {
        float v0 = ts[c][tid], v1 = ts[c + 1][tid];
        float v2 = ts[c + 2][tid], v3 = ts[c + 3][tid];
        #pragma unroll
        for (int o = 0; o < 64; o++) {
            float4 w4 = *(const float4*)&ws[o * 64 + c];
            acc[o] = fmaf(w4.x, v0, acc[o]);
            acc[o] = fmaf(w4.y, v1, acc[o]);
            acc[o] = fmaf(w4.z, v2, acc[o]);
            acc[o] = fmaf(w4.w, v3, acc[o]);
        }
    }
    #pragma unroll
    for (int o = 0; o < 64; o++)
        g_v[(b * 64 + o) * NDS + n] = fmaxf(acc[o] + __ldg(&vb[o]), 0.0f);
    __syncthreads();

    // k from g_efd (gmem)
    #pragma unroll
    for (int i = 0; i < 32; i++) ws[i * 128 + tid] = kw[i * 128 + tid];
    __syncthreads();
    #pragma unroll
    for (int o = 0; o < 64; o++) acc[o] = 0.0f;
    const float* pef = g_efd + (b * 64) * NDS + n;
    #pragma unroll 1
    for (int c = 0; c < 64; c += 4) {
        float v0 = pef[c * NDS],       v1 = pef[(c + 1) * NDS];
        float v2 = pef[(c + 2) * NDS], v3 = pef[(c + 3) * NDS];
        #pragma unroll
        for (int o = 0; o < 64; o++) {
            float4 w4 = *(const float4*)&ws[o * 64 + c];
            acc[o] = fmaf(w4.x, v0, acc[o]);
            acc[o] = fmaf(w4.y, v1, acc[o]);
            acc[o] = fmaf(w4.z, v2, acc[o]);
            acc[o] = fmaf(w4.w, v3, acc[o]);
        }
    }
    #pragma unroll
    for (int o = 0; o < 64; o++)
        g_k[(b * 64 + o) * NDS + n] = fmaxf(acc[o] + __ldg(&kb[o]), 0.0f);
}

// ============================================================================
// K4: flash attention, fp32. energy[m,n] = sum_d q[d,m]*k[d,n];
// softmax over n; O[d,m] = sum_n P[m,n]*v[d,n].
// Block: 64 m-rows, 256 threads (16x16), 4x4 register tiles, 64-wide n tiles.
// smem: qs[64][68] (float4 reads), ks[64][65] (aliased as P), vs[64][65].
// ============================================================================
#define ATTN_SMEM ((64 * 68 + 2 * 64 * 65) * 4)

__global__ __launch_bounds__(256) void attn_kernel()
{
    extern __shared__ float sm[];
    float* qs = sm;                 // [64][68]
    float* ks = sm + 64 * 68;       // [64][65], reused as P after S-GEMM
    float* vs = ks + 64 * 65;       // [64][65]

    int tid = threadIdx.x;
    int tx = tid & 15, ty = tid >> 4;
    int b  = blockIdx.y;
    int m0 = blockIdx.x << 6;

    const float* qg = g_q + (b * 64) * NDS;
    const float* kg = g_k + (b * 64) * NDS;
    const float* vg = g_v + (b * 64) * NDS;

    for (int i = tid; i < 4096; i += 256) {
        int d = i >> 6, m = i & 63;
        qs[d * 68 + m] = qg[d * NDS + m0 + m];
    }

    float mrow[4], lrow[4], Oc[4][4];
    #pragma unroll
    for (int im = 0; im < 4; im++) {
        mrow[im] = -1e30f; lrow[im] = 0.0f;
        #pragma unroll
        for (int id = 0; id < 4; id++) Oc[im][id] = 0.0f;
    }

    for (int nt = 0; nt < 64; nt++) {
        int n0 = nt << 6;
        __syncthreads();   // previous iteration's P/V reads (and qs writes) done
        for (int i = tid; i < 4096; i += 256) {
            int d = i >> 6, n = i & 63;
            ks[d * 65 + n] = kg[d * NDS + n0 + n];
            vs[d * 65 + n] = vg[d * NDS + n0 + n];
        }
        __syncthreads();

        float S[4][4];
        #pragma unroll
        for (int im = 0; im < 4; im++)
            #pragma unroll
            for (int in = 0; in < 4; in++) S[im][in] = 0.0f;

        #pragma unroll
        for (int d = 0; d < 64; d++) {
            float4 q4 = *(const float4*)&qs[d * 68 + (ty << 2)];
            float k0 = ks[d * 65 + (tx << 2) + 0];
            float k1 = ks[d * 65 + (tx << 2) + 1];
            float k2 = ks[d * 65 + (tx << 2) + 2];
            float k3 = ks[d * 65 + (tx << 2) + 3];
            S[0][0] = fmaf(q4.x, k0, S[0][0]); S[0][1] = fmaf(q4.x, k1, S[0][1]);
            S[0][2] = fmaf(q4.x, k2, S[0][2]); S[0][3] = fmaf(q4.x, k3, S[0][3]);
            S[1][0] = fmaf(q4.y, k0, S[1][0]); S[1][1] = fmaf(q4.y, k1, S[1][1]);
            S[1][2] = fmaf(q4.y, k2, S[1][2]); S[1][3] = fmaf(q4.y, k3, S[1][3]);
            S[2][0] = fmaf(q4.z, k0, S[2][0]); S[2][1] = fmaf(q4.z, k1, S[2][1]);
            S[2][2] = fmaf(q4.z, k2, S[2][2]); S[2][3] = fmaf(q4.z, k3, S[2][3]);
            S[3][0] = fmaf(q4.w, k0, S[3][0]); S[3][1] = fmaf(q4.w, k1, S[3][1]);
            S[3][2] = fmaf(q4.w, k2, S[3][2]); S[3][3] = fmaf(q4.w, k3, S[3][3]);
        }
        __syncthreads();   // all ks reads done before P overwrites it

        #pragma unroll
        for (int im = 0; im < 4; im++) {
            float tm = fmaxf(fmaxf(S[im][0], S[im][1]), fmaxf(S[im][2], S[im][3]));
            tm = fmaxf(tm, __shfl_xor_sync(0xffffffffu, tm, 1));
            tm = fmaxf(tm, __shfl_xor_sync(0xffffffffu, tm, 2));
            tm = fmaxf(tm, __shfl_xor_sync(0xffffffffu, tm, 4));
            tm = fmaxf(tm, __shfl_xor_sync(0xffffffffu, tm, 8));
            float mn   = fmaxf(mrow[im], tm);
            float corr = __expf(mrow[im] - mn);
            mrow[im] = mn;
            float rs = 0.0f;
            #pragma unroll
            for (int in = 0; in < 4; in++) {
                float pv = __expf(S[im][in] - mn);
                S[im][in] = pv;
                rs += pv;
            }
            rs += __shfl_xor_sync(0xffffffffu, rs, 1);
            rs += __shfl_xor_sync(0xffffffffu, rs, 2);
            rs += __shfl_xor_sync(0xffffffffu, rs, 4);
            rs += __shfl_xor_sync(0xffffffffu, rs, 8);
            lrow[im] = lrow[im] * corr + rs;
            #pragma unroll
            for (int id = 0; id < 4; id++) Oc[im][id] *= corr;
            #pragma unroll
            for (int in = 0; in < 4; in++)
                ks[((ty << 2) + im) * 65 + (tx << 2) + in] = S[im][in];  // P
        }
        __syncthreads();

        // O += P @ V^T  (P in ks, V in vs)
        #pragma unroll 4
        for (int n = 0; n < 64; n++) {
            float p0 = ks[((ty << 2) + 0) * 65 + n];
            float p1 = ks[((ty << 2) + 1) * 65 + n];
            float p2 = ks[((ty << 2) + 2) * 65 + n];
            float p3 = ks[((ty << 2) + 3) * 65 + n];
            float v0 = vs[((tx << 2) + 0) * 65 + n];
            float v1 = vs[((tx << 2) + 1) * 65 + n];
            float v2 = vs[((tx << 2) + 2) * 65 + n];
            float v3 = vs[((tx << 2) + 3) * 65 + n];
            Oc[0][0] = fmaf(p0, v0, Oc[0][0]); Oc[0][1] = fmaf(p0, v1, Oc[0][1]);
            Oc[0][2] = fmaf(p0, v2, Oc[0][2]); Oc[0][3] = fmaf(p0, v3, Oc[0][3]);
            Oc[1][0] = fmaf(p1, v0, Oc[1][0]); Oc[1][1] = fmaf(p1, v1, Oc[1][1]);
            Oc[1][2] = fmaf(p1, v2, Oc[1][2]); Oc[1][3] = fmaf(p1, v3, Oc[1][3]);
            Oc[2][0] = fmaf(p2, v0, Oc[2][0]); Oc[2][1] = fmaf(p2, v1, Oc[2][1]);
            Oc[2][2] = fmaf(p2, v2, Oc[2][2]); Oc[2][3] = fmaf(p2, v3, Oc[2][3]);
            Oc[3][0] = fmaf(p3, v0, Oc[3][0]); Oc[3][1] = fmaf(p3, v1, Oc[3][1]);
            Oc[3][2] = fmaf(p3, v2, Oc[3][2]); Oc[3][3] = fmaf(p3, v3, Oc[3][3]);
        }
    }

    #pragma unroll
    for (int im = 0; im < 4; im++) {
        float inv = 1.0f / lrow[im];
        #pragma unroll
        for (int id = 0; id < 4; id++) {
            int c = (tx << 2) + id;
            int m = m0 + (ty << 2) + im;
            g_O[(b * 64 + c) * NDS + m] = Oc[im][id] * inv;
        }
    }
}

// ============================================================================
// K5: epilogue. First half: out += THITA*gamma*up4(O) (x is already there).
//     Second half: ef_up = up4(ef_d).
// float4 over x; x..x+3 share the same source pixel (x>>2).
// ============================================================================
__global__ __launch_bounds__(256) void epilogue_kernel(
    const float* __restrict__ gamma, float* __restrict__ out)
{
    int i4 = blockIdx.x * 256 + threadIdx.x;
    const int HALF4 = (BATCH * CHN * HW) >> 2;       // 4194304
    float tg = THITA_F * __ldg(gamma);
    float4* o4 = (float4*)out;

    if (i4 < HALF4) {
        int e  = i4 << 2;
        int bc = e >> 16;
        int p  = e & 65535;
        int y = p >> 8, x = p & 255;
        int nd = ((y >> 2) << 6) + (x >> 2);
        float add = tg * g_O[bc * NDS + nd];
        float4 cur = o4[i4];
        cur.x += add; cur.y += add; cur.z += add; cur.w += add;
        o4[i4] = cur;
    } else {
        int j  = i4 - HALF4;
        int e  = j << 2;
        int bc = e >> 16;
        int p  = e & 65535;
        int y = p >> 8, x = p & 255;
        float val = g_efd[bc * NDS + ((y >> 2) << 6) + (x >> 2)];
        o4[i4] = make_float4(val, val, val, val);
    }
}

// ============================================================================
extern "C" void kernel_launch(void* const* d_in, const int* in_sizes, int n_in,
                              void* d_out, int out_size)
{
    const float* x1    = (const float*)d_in[0];
    const float* x2    = (const float*)d_in[1];
    const float* ev    = (const float*)d_in[2];
    const float* xw0   = (const float*)d_in[3];
    const float* xb0   = (const float*)d_in[4];
    const float* xw1   = (const float*)d_in[5];
    const float* xb1   = (const float*)d_in[6];
    const float* ew0   = (const float*)d_in[7];
    const float* eb0   = (const float*)d_in[8];
    const float* ew1   = (const float*)d_in[9];
    const float* eb1   = (const float*)d_in[10];
    const float* qw    = (const float*)d_in[11];
    const float* qb    = (const float*)d_in[12];
    const float* kw    = (const float*)d_in[13];
    const float* kb    = (const float*)d_in[14];
    const float* vw    = (const float*)d_in[15];
    const float* vb    = (const float*)d_in[16];
    const float* gamma = (const float*)d_in[17];
    float* out = (float*)d_out;

    cudaFuncSetAttribute(attn_kernel,
                         cudaFuncAttributeMaxDynamicSharedMemorySize, ATTN_SMEM);

    conv0_kernel<<<dim3(HW / 128, BATCH), 128>>>(x1, x2, xw0, xb0, out);
    ef_kernel<<<dim3(NDS / 128, BATCH), 128>>>(ev, ew0, eb0, ew1, eb1);
    qkv_kernel<<<dim3(NDS / 128, BATCH), 128>>>(out, xw1, xb1, qw, qb, kw, kb, vw, vb);
    attn_kernel<<<dim3(NDS / 64, BATCH), 256, ATTN_SMEM>>>();
    epilogue_kernel<<<(2 * BATCH * CHN * HW / 4) / 256, 256>>>(gamma, out);
}

// round 2
// speedup vs baseline: 2.5164x; 2.5164x over previous
#include <cuda_runtime.h>
#include <cuda_fp16.h>
#include <math.h>

#define BATCH 4
#define CHN 64
#define HW 65536        // 256*256
#define NDS 4096        // 64*64 downsampled pixels
#define THITA_F 1.0e-4f

// ---------------- scratch (device globals; no allocations allowed) ----------
__device__ float  g_efd[BATCH * CHN * NDS];     // ef after 2nd conv (fp32, feeds ef_up)
__device__ __half g_qh[BATCH * NDS * CHN];      // [b][n][d] f16
__device__ __half g_kh[BATCH * NDS * CHN];
__device__ __half g_vh[BATCH * NDS * CHN];
__device__ float  g_O[BATCH * CHN * NDS];       // attention output [b][d][m]
__device__ float  g_w0t[192 * 64];              // conv0 weights transposed [c][o]

// ============================================================================
// K0: transpose conv0 weights w[o][c] -> g_w0t[c][o] (once, tiny)
// ============================================================================
__global__ void wt_kernel(const float* __restrict__ w) {
    int i = blockIdx.x * 256 + threadIdx.x;
    if (i < 192 * 64) {
        int c = i >> 6, o = i & 63;
        g_w0t[c * 64 + o] = w[o * 192 + c];
    }
}

// ============================================================================
// K1: x = relu(xw0 @ concat(x1,x2) + xb0) at full res, packed f32x2 FFMA2.
// acc[j] packs outputs (2j, 2j+1). ws is [c][o] so o-pairs are adjacent.
// ============================================================================
__global__ __launch_bounds__(128) void conv0_kernel(
    const float* __restrict__ x1, const float* __restrict__ x2,
    const float* __restrict__ bias, float* __restrict__ out)
{
    __shared__ float ws[192 * 64];   // 48 KB, [c][o]
    int tid = threadIdx.x;
    #pragma unroll
    for (int i = 0; i < 96; i++) ws[i * 128 + tid] = g_w0t[i * 128 + tid];
    __syncthreads();

    int b = blockIdx.y;
    int p = (blockIdx.x << 7) + tid;
    const float* px1 = x1 + (size_t)b * 128 * HW + p;
    const float* px2 = x2 + (size_t)b * 64  * HW + p;

    unsigned long long acc[32];
    #pragma unroll
    for (int j = 0; j < 32; j++) acc[j] = 0ull;

    #pragma unroll 4
    for (int c = 0; c < 128; c++) {
        float v = px1[(size_t)c * HW];
        unsigned long long vv;
        asm("mov.b64 %0, {%1, %1};" : "=l"(vv) : "f"(v));
        const ulonglong2* wp = (const ulonglong2*)(ws + c * 64);
        #pragma unroll
        for (int j = 0; j < 16; j++) {
            ulonglong2 w2 = wp[j];
            asm("fma.rn.f32x2 %0, %1, %2, %0;" : "+l"(acc[2*j])   : "l"(w2.x), "l"(vv));
            asm("fma.rn.f32x2 %0, %1, %2, %0;" : "+l"(acc[2*j+1]) : "l"(w2.y), "l"(vv));
        }
    }
    #pragma unroll 4
    for (int c = 0; c < 64; c++) {
        float v = px2[(size_t)c * HW];
        unsigned long long vv;
        asm("mov.b64 %0, {%1, %1};" : "=l"(vv) : "f"(v));
        const ulonglong2* wp = (const ulonglong2*)(ws + (128 + c) * 64);
        #pragma unroll
        for (int j = 0; j < 16; j++) {
            ulonglong2 w2 = wp[j];
            asm("fma.rn.f32x2 %0, %1, %2, %0;" : "+l"(acc[2*j])   : "l"(w2.x), "l"(vv));
            asm("fma.rn.f32x2 %0, %1, %2, %0;" : "+l"(acc[2*j+1]) : "l"(w2.y), "l"(vv));
        }
    }

    float* po = out + (size_t)b * 64 * HW + p;
    #pragma unroll
    for (int j = 0; j < 32; j++) {
        float lo, hi;
        asm("mov.b64 {%0, %1}, %2;" : "=f"(lo), "=f"(hi) : "l"(acc[j]));
        po[(size_t)(2*j)   * HW] = fmaxf(lo + __ldg(&bias[2*j]),   0.0f);
        po[(size_t)(2*j+1) * HW] = fmaxf(hi + __ldg(&bias[2*j+1]), 0.0f);
    }
}

// ============================================================================
// K2: ef path at downsampled pixels only (fp32, unchanged)
// ============================================================================
__global__ __launch_bounds__(128) void ef_kernel(
    const float* __restrict__ event,
    const float* __restrict__ w0, const float* __restrict__ b0,
    const float* __restrict__ w1, const float* __restrict__ b1)
{
    __shared__ float ws[64 * 64];
    __shared__ float ts[64][128];
    int tid = threadIdx.x;
    int b   = blockIdx.y;
    int n   = (blockIdx.x << 7) + tid;
    int p   = ((n >> 6) << 10) + ((n & 63) << 2);

    float acc[64];

    #pragma unroll
    for (int i = 0; i < 32; i++) ws[i * 128 + tid] = w0[i * 128 + tid];
    __syncthreads();
    #pragma unroll
    for (int o = 0; o < 64; o++) acc[o] = 0.0f;
    const float* pe = event + (size_t)b * 64 * HW + p;
    #pragma unroll 1
    for (int c = 0; c < 64; c += 4) {
        float v0 = pe[(size_t)c * HW];
        float v1 = pe[(size_t)(c + 1) * HW];
        float v2 = pe[(size_t)(c + 2) * HW];
        float v3 = pe[(size_t)(c + 3) * HW];
        #pragma unroll
        for (int o = 0; o < 64; o++) {
            float4 w4 = *(const float4*)&ws[o * 64 + c];
            acc[o] = fmaf(w4.x, v0, acc[o]);
            acc[o] = fmaf(w4.y, v1, acc[o]);
            acc[o] = fmaf(w4.z, v2, acc[o]);
            acc[o] = fmaf(w4.w, v3, acc[o]);
        }
    }
    #pragma unroll
    for (int o = 0; o < 64; o++) ts[o][tid] = fmaxf(acc[o] + __ldg(&b0[o]), 0.0f);
    __syncthreads();

    #pragma unroll
    for (int i = 0; i < 32; i++) ws[i * 128 + tid] = w1[i * 128 + tid];
    __syncthreads();
    #pragma unroll
    for (int o = 0; o < 64; o++) acc[o] = 0.0f;
    #pragma unroll 1
    for (int c = 0; c < 64; c += 4) {
        float v0 = ts[c][tid], v1 = ts[c + 1][tid];
        float v2 = ts[c + 2][tid], v3 = ts[c + 3][tid];
        #pragma unroll
        for (int o = 0; o < 64; o++) {
            float4 w4 = *(const float4*)&ws[o * 64 + c];
            acc[o] = fmaf(w4.x, v0, acc[o]);
            acc[o] = fmaf(w4.y, v1, acc[o]);
            acc[o] = fmaf(w4.z, v2, acc[o]);
            acc[o] = fmaf(w4.w, v3, acc[o]);
        }
    }
    float* pd = g_efd + (b * 64) * NDS + n;
    #pragma unroll
    for (int o = 0; o < 64; o++) pd[o * NDS] = fmaxf(acc[o] + __ldg(&b1[o]), 0.0f);
}

// ============================================================================
// K3: q/k/v, outputs f16 in [b][n][d] layout (for ldmatrix in attention)
// ============================================================================
__device__ __forceinline__ void store_h16(__half* dst, const float* acc,
                                          const float* bias)
{
    #pragma unroll
    for (int j = 0; j < 8; j++) {
        union { uint4 u; __half2 h2[4]; } U;
        #pragma unroll
        for (int q = 0; q < 4; q++) {
            int o = 8 * j + 2 * q;
            float r0 = fmaxf(acc[o]     + __ldg(&bias[o]),     0.0f);
            float r1 = fmaxf(acc[o + 1] + __ldg(&bias[o + 1]), 0.0f);
            U.h2[q] = __floats2half2_rn(r0, r1);
        }
        ((uint4*)dst)[j] = U.u;
    }
}

__global__ __launch_bounds__(128) void qkv_kernel(
    const float* __restrict__ xsrc,
    const float* __restrict__ xw1, const float* __restrict__ xb1,
    const float* __restrict__ qw,  const float* __restrict__ qb,
    const float* __restrict__ kw,  const float* __restrict__ kb,
    const float* __restrict__ vw,  const float* __restrict__ vb)
{
    __shared__ float ws[64 * 64];
    __shared__ float ts[64][128];
    int tid = threadIdx.x;
    int b   = blockIdx.y;
    int n   = (blockIdx.x << 7) + tid;
    int p   = ((n >> 6) << 10) + ((n & 63) << 2);

    float acc[64];

    // t = relu(xw1 @ x_ds + xb1)
    #pragma unroll
    for (int i = 0; i < 32; i++) ws[i * 128 + tid] = xw1[i * 128 + tid];
    __syncthreads();
    #pragma unroll
    for (int o = 0; o < 64; o++) acc[o] = 0.0f;
    const float* px = xsrc + (size_t)b * 64 * HW + p;
    #pragma unroll 1
    for (int c = 0; c < 64; c += 4) {
        float v0 = px[(size_t)c * HW];
        float v1 = px[(size_t)(c + 1) * HW];
        float v2 = px[(size_t)(c + 2) * HW];
        float v3 = px[(size_t)(c + 3) * HW];
        #pragma unroll
        for (int o = 0; o < 64; o++) {
            float4 w4 = *(const float4*)&ws[o * 64 + c];
            acc[o] = fmaf(w4.x, v0, acc[o]);
            acc[o] = fmaf(w4.y, v1, acc[o]);
            acc[o] = fmaf(w4.z, v2, acc[o]);
            acc[o] = fmaf(w4.w, v3, acc[o]);
        }
    }
    #pragma unroll
    for (int o = 0; o < 64; o++) ts[o][tid] = fmaxf(acc[o] + __ldg(&xb1[o]), 0.0f);
    __syncthreads();

    // q
    #pragma unroll
    for (int i = 0; i < 32; i++) ws[i * 128 + tid] = qw[i * 128 + tid];
    __syncthreads();
    #pragma unroll
    for (int o = 0; o < 64; o++) acc[o] = 0.0f;
    #pragma unroll 1
    for (int c = 0; c < 64; c += 4) {
        float v0 = ts[c][tid], v1 = ts[c + 1][tid];
        float v2 = ts[c + 2][tid], v3 = ts[c + 3][tid];
        #pragma unroll
        for (int o = 0; o < 64; o++) {
            float4 w4 = *(const float4*)&ws[o * 64 + c];
            acc[o] = fmaf(w4.x, v0, acc[o]);
            acc[o] = fmaf(w4.y, v1, acc[o]);
            acc[o] = fmaf(w4.z, v2, acc[o]);
            acc[o] = fmaf(w4.w, v3, acc[o]);
        }
    }
    store_h16(g_qh + ((size_t)b * NDS + n) * 64, acc, qb);
    __syncthreads();

    // v
    #pragma unroll
    for (int i = 0; i < 32; i++) ws[i * 128 + tid] = vw[i * 128 + tid];
    __syncthreads();
    #pragma unroll
    for (int o = 0; o < 64; o++) acc[o] = 0.0f;
    #pragma unroll 1
    for (int c = 0; c < 64; c += 4) {
        float v0 = ts[c][tid], v1 = ts[c + 1][tid];
        float v2 = ts[c + 2][tid], v3 = ts[c + 3][tid];
        #pragma unroll
        for (int o = 0; o < 64; o++) {
            float4 w4 = *(const float4*)&ws[o * 64 + c];
            acc[o] = fmaf(w4.x, v0, acc[o]);
            acc[o] = fmaf(w4.y, v1, acc[o]);
            acc[o] = fmaf(w4.z, v2, acc[o]);
            acc[o] = fmaf(w4.w, v3, acc[o]);
        }
    }
    store_h16(g_vh + ((size_t)b * NDS + n) * 64, acc, vb);
    __syncthreads();

    // k from g_efd
    #pragma unroll
    for (int i = 0; i < 32; i++) ws[i * 128 + tid] = kw[i * 128 + tid];
    __syncthreads();
    #pragma unroll
    for (int o = 0; o < 64; o++) acc[o] = 0.0f;
    const float* pef = g_efd + (b * 64) * NDS + n;
    #pragma unroll 1
    for (int c = 0; c < 64; c += 4) {
        float v0 = pef[c * NDS],       v1 = pef[(c + 1) * NDS];
        float v2 = pef[(c + 2) * NDS], v3 = pef[(c + 3) * NDS];
        #pragma unroll
        for (int o = 0; o < 64; o++) {
            float4 w4 = *(const float4*)&ws[o * 64 + c];
            acc[o] = fmaf(w4.x, v0, acc[o]);
            acc[o] = fmaf(w4.y, v1, acc[o]);
            acc[o] = fmaf(w4.z, v2, acc[o]);
            acc[o] = fmaf(w4.w, v3, acc[o]);
        }
    }
    store_h16(g_kh + ((size_t)b * NDS + n) * 64, acc, kb);
}

// ============================================================================
// K4: flash attention, f16 mma.sync.m16n8k16 + Schraudolph exp2.
// Block: 256 thr (8 warps), M-tile 128 (16 rows/warp), N-tile 64, 64 iters.
// smem: Q [128][72] f16, K/V double-buffered [64][72] f16 each.
// ============================================================================
#define SM_STRIDE 72
#define ATTN_SMEM ((128 * SM_STRIDE + 4 * 64 * SM_STRIDE) * 2)

__device__ __forceinline__ void mma16816(float* d,
    unsigned a0, unsigned a1, unsigned a2, unsigned a3,
    unsigned b0, unsigned b1)
{
    asm volatile(
        "mma.sync.aligned.m16n8k16.row.col.f32.f16.f16.f32 "
        "{%0,%1,%2,%3}, {%4,%5,%6,%7}, {%8,%9}, {%0,%1,%2,%3};\n"
        : "+f"(d[0]), "+f"(d[1]), "+f"(d[2]), "+f"(d[3])
        : "r"(a0), "r"(a1), "r"(a2), "r"(a3), "r"(b0), "r"(b1));
}
__device__ __forceinline__ void ldm4(unsigned* r, unsigned a) {
    asm volatile("ldmatrix.sync.aligned.m8n8.x4.shared.b16 {%0,%1,%2,%3}, [%4];\n"
        : "=r"(r[0]), "=r"(r[1]), "=r"(r[2]), "=r"(r[3]) : "r"(a));
}
__device__ __forceinline__ void ldm4t(unsigned* r, unsigned a) {
    asm volatile("ldmatrix.sync.aligned.m8n8.x4.trans.shared.b16 {%0,%1,%2,%3}, [%4];\n"
        : "=r"(r[0]), "=r"(r[1]), "=r"(r[2]), "=r"(r[3]) : "r"(a));
}
__device__ __forceinline__ void cpasync16(unsigned dst, const void* src) {
    asm volatile("cp.async.cg.shared.global [%0], [%1], 16;\n"
        :: "r"(dst), "l"(src));
}
// Schraudolph exp(s - m): bits = s*EXPA + (EXPB - m*EXPA), clamped to >= 0
__device__ __forceinline__ float sexp(float s, float c) {
    float t = fmaf(s, 12102203.16f, c);
    t = fmaxf(t, 0.0f);
    return __int_as_float(__float2int_rn(t));
}
__device__ __forceinline__ unsigned packh2(float a, float b) {
    __half2 h = __floats2half2_rn(a, b);
    return *(unsigned*)&h;
}

__global__ __launch_bounds__(256, 1) void attn_kernel()
{
    extern __shared__ __half smh[];
    __half* qs  = smh;                        // 128 x 72
    __half* ks0 = smh + 128 * SM_STRIDE;      // 2 buffers of 64 x 72
    __half* vs0 = ks0 + 2 * 64 * SM_STRIDE;   // 2 buffers of 64 x 72

    int tid  = threadIdx.x;
    int lane = tid & 31, w = tid >> 5;
    int gid  = lane >> 2, tig = lane & 3;
    int b    = blockIdx.y;
    int m0   = blockIdx.x << 7;

    const __half* qg = g_qh + (size_t)b * NDS * 64;
    const __half* kg = g_kh + (size_t)b * NDS * 64;
    const __half* vg = g_vh + (size_t)b * NDS * 64;

    unsigned qs_base = (unsigned)__cvta_generic_to_shared(qs);
    unsigned ks_base = (unsigned)__cvta_generic_to_shared(ks0);
    unsigned vs_base = (unsigned)__cvta_generic_to_shared(vs0);

    // prefetch K/V tile 0 into buffer 0
    #pragma unroll
    for (int rep = 0; rep < 2; rep++) {
        int c = tid + rep * 256;          // 0..511
        int row = c >> 3, off = c & 7;
        cpasync16(ks_base + (row * SM_STRIDE + off * 8) * 2, kg + row * 64 + off * 8);
        cpasync16(vs_base + (row * SM_STRIDE + off * 8) * 2, vg + row * 64 + off * 8);
    }
    asm volatile("cp.async.commit_group;\n");

    // load Q tile (plain)
    for (int c = tid; c < 1024; c += 256) {
        int row = c >> 3, off = c & 7;
        *(uint4*)(qs + row * SM_STRIDE + off * 8) =
            *(const uint4*)(qg + (size_t)(m0 + row) * 64 + off * 8);
    }
    asm volatile("cp.async.wait_group 0;\n");
    __syncthreads();

    // Q A-fragments (persist): qa[kc][0..3]
    unsigned qa[4][4];
    {
        int row = (w << 4) + (lane & 7) + ((lane >> 3) & 1) * 8;
        #pragma unroll
        for (int kc = 0; kc < 4; kc++) {
            int dof = kc * 16 + (lane >> 4) * 8;
            ldm4(qa[kc], qs_base + (row * SM_STRIDE + dof) * 2);
        }
    }

    float Of[8][4];
    #pragma unroll
    for (int dc = 0; dc < 8; dc++)
        #pragma unroll
        for (int q = 0; q < 4; q++) Of[dc][q] = 0.0f;
    float mrow0 = -1e30f, mrow1 = -1e30f, lrow0 = 0.0f, lrow1 = 0.0f;
    const unsigned ONES = 0x3C003C00u;

    for (int it = 0; it < 64; it++) {
        int bf = it & 1;
        unsigned ksb = ks_base + bf * 64 * SM_STRIDE * 2;
        unsigned vsb = vs_base + bf * 64 * SM_STRIDE * 2;

        if (it + 1 < 64) {  // prefetch next tile into other buffer
            int n0n = (it + 1) << 6;
            int nb  = (it + 1) & 1;
            #pragma unroll
            for (int rep = 0; rep < 2; rep++) {
                int c = tid + rep * 256;
                int row = c >> 3, off = c & 7;
                cpasync16(ks_base + (nb * 64 * SM_STRIDE + row * SM_STRIDE + off * 8) * 2,
                          kg + (size_t)(n0n + row) * 64 + off * 8);
                cpasync16(vs_base + (nb * 64 * SM_STRIDE + row * SM_STRIDE + off * 8) * 2,
                          vg + (size_t)(n0n + row) * 64 + off * 8);
            }
            asm volatile("cp.async.commit_group;\n");
        }

        // S = Q @ K^T  (16 x 64 per warp)
        float S[8][4];
        #pragma unroll
        for (int nc = 0; nc < 8; nc++) {
            unsigned kb[8];
            int krow = nc * 8 + (lane & 7);
            int kd   = (lane >> 3) * 8;
            ldm4(kb,     ksb + (krow * SM_STRIDE + kd) * 2);        // kc 0,1
            ldm4(kb + 4, ksb + (krow * SM_STRIDE + 32 + kd) * 2);   // kc 2,3
            #pragma unroll
            for (int q = 0; q < 4; q++) S[nc][q] = 0.0f;
            mma16816(S[nc], qa[0][0], qa[0][1], qa[0][2], qa[0][3], kb[0], kb[1]);
            mma16816(S[nc], qa[1][0], qa[1][1], qa[1][2], qa[1][3], kb[2], kb[3]);
            mma16816(S[nc], qa[2][0], qa[2][1], qa[2][2], qa[2][3], kb[4], kb[5]);
            mma16816(S[nc], qa[3][0], qa[3][1], qa[3][2], qa[3][3], kb[6], kb[7]);
        }

        // online softmax
        float tm0 = fmaxf(S[0][0], S[0][1]);
        float tm1 = fmaxf(S[0][2], S[0][3]);
        #pragma unroll
        for (int nc = 1; nc < 8; nc++) {
            tm0 = fmaxf(tm0, fmaxf(S[nc][0], S[nc][1]));
            tm1 = fmaxf(tm1, fmaxf(S[nc][2], S[nc][3]));
        }
        tm0 = fmaxf(tm0, __shfl_xor_sync(0xffffffffu, tm0, 1));
        tm0 = fmaxf(tm0, __shfl_xor_sync(0xffffffffu, tm0, 2));
        tm1 = fmaxf(tm1, __shfl_xor_sync(0xffffffffu, tm1, 1));
        tm1 = fmaxf(tm1, __shfl_xor_sync(0xffffffffu, tm1, 2));
        float nm0 = fmaxf(mrow0, tm0), nm1 = fmaxf(mrow1, tm1);
        float sc0 = exp2f((mrow0 - nm0) * 1.44269504f);
        float sc1 = exp2f((mrow1 - nm1) * 1.44269504f);
        mrow0 = nm0; mrow1 = nm1;
        float c0 = 1064866805.0f - nm0 * 12102203.16f;
        float c1 = 1064866805.0f - nm1 * 12102203.16f;

        // P as A-fragments (f16x2)
        unsigned P[4][4];
        #pragma unroll
        for (int jc = 0; jc < 4; jc++) {
            P[jc][0] = packh2(sexp(S[2*jc][0],   c0), sexp(S[2*jc][1],   c0));
            P[jc][1] = packh2(sexp(S[2*jc][2],   c1), sexp(S[2*jc][3],   c1));
            P[jc][2] = packh2(sexp(S[2*jc+1][0], c0), sexp(S[2*jc+1][1], c0));
            P[jc][3] = packh2(sexp(S[2*jc+1][2], c1), sexp(S[2*jc+1][3], c1));
        }

        // row sums via ones-mma
        float lf[4] = {0.0f, 0.0f, 0.0f, 0.0f};
        #pragma unroll
        for (int jc = 0; jc < 4; jc++)
            mma16816(lf, P[jc][0], P[jc][1], P[jc][2], P[jc][3], ONES, ONES);
        lrow0 = lrow0 * sc0 + lf[0];
        lrow1 = lrow1 * sc1 + lf[2];

        // rescale O
        #pragma unroll
        for (int dc = 0; dc < 8; dc++) {
            Of[dc][0] *= sc0; Of[dc][1] *= sc0;
            Of[dc][2] *= sc1; Of[dc][3] *= sc1;
        }

        // O += P @ V
        #pragma unroll
        for (int jc = 0; jc < 4; jc++) {
            int vrow = jc * 16 + (lane & 7) + ((lane >> 3) & 1) * 8;
            int vcb  = (lane >> 4) * 8;
            #pragma unroll
            for (int dcp = 0; dcp < 4; dcp++) {
                unsigned vb[4];
                ldm4t(vb, vsb + (vrow * SM_STRIDE + dcp * 16 + vcb) * 2);
                mma16816(Of[2*dcp],     P[jc][0], P[jc][1], P[jc][2], P[jc][3], vb[0], vb[1]);
                mma16816(Of[2*dcp + 1], P[jc][0], P[jc][1], P[jc][2], P[jc][3], vb[2], vb[3]);
            }
        }

        if (it + 1 < 64) {
            asm volatile("cp.async.wait_group 0;\n");
            __syncthreads();
        }
    }

    float inv0 = 1.0f / lrow0, inv1 = 1.0f / lrow1;
    int m = m0 + (w << 4) + gid;
    #pragma unroll
    for (int dc = 0; dc < 8; dc++) {
        int d0 = dc * 8 + tig * 2;
        g_O[(b * 64 + d0)     * NDS + m]     = Of[dc][0] * inv0;
        g_O[(b * 64 + d0 + 1) * NDS + m]     = Of[dc][1] * inv0;
        g_O[(b * 64 + d0)     * NDS + m + 8] = Of[dc][2] * inv1;
        g_O[(b * 64 + d0 + 1) * NDS + m + 8] = Of[dc][3] * inv1;
    }
}

// ============================================================================
// K5: epilogue. out += THITA*gamma*up4(O); ef_up = up4(ef_d).
// ============================================================================
__global__ __launch_bounds__(256) void epilogue_kernel(
    const float* __restrict__ gamma, float* __restrict__ out)
{
    int i4 = blockIdx.x * 256 + threadIdx.x;
    const int HALF4 = (BATCH * CHN * HW) >> 2;
    float tg = THITA_F * __ldg(gamma);
    float4* o4 = (float4*)out;

    if (i4 < HALF4) {
        int e  = i4 << 2;
        int bc = e >> 16;
        int p  = e & 65535;
        int y = p >> 8, x = p & 255;
        int nd = ((y >> 2) << 6) + (x >> 2);
        float add = tg * g_O[bc * NDS + nd];
        float4 cur = o4[i4];
        cur.x += add; cur.y += add; cur.z += add; cur.w += add;
        o4[i4] = cur;
    } else {
        int j  = i4 - HALF4;
        int e  = j << 2;
        int bc = e >> 16;
        int p  = e & 65535;
        int y = p >> 8, x = p & 255;
        float val = g_efd[bc * NDS + ((y >> 2) << 6) + (x >> 2)];
        o4[i4] = make_float4(val, val, val, val);
    }
}

// ============================================================================
extern "C" void kernel_launch(void* const* d_in, const int* in_sizes, int n_in,
                              void* d_out, int out_size)
{
    const float* x1    = (const float*)d_in[0];
    const float* x2    = (const float*)d_in[1];
    const float* ev    = (const float*)d_in[2];
    const float* xw0   = (const float*)d_in[3];
    const float* xb0   = (const float*)d_in[4];
    const float* xw1   = (const float*)d_in[5];
    const float* xb1   = (const float*)d_in[6];
    const float* ew0   = (const float*)d_in[7];
    const float* eb0   = (const float*)d_in[8];
    const float* ew1   = (const float*)d_in[9];
    const float* eb1   = (const float*)d_in[10];
    const float* qw    = (const float*)d_in[11];
    const float* qb    = (const float*)d_in[12];
    const float* kw    = (const float*)d_in[13];
    const float* kb    = (const float*)d_in[14];
    const float* vw    = (const float*)d_in[15];
    const float* vb    = (const float*)d_in[16];
    const float* gamma = (const float*)d_in[17];
    float* out = (float*)d_out;

    cudaFuncSetAttribute(attn_kernel,
                         cudaFuncAttributeMaxDynamicSharedMemorySize, ATTN_SMEM);

    wt_kernel<<<48, 256>>>(xw0);
    conv0_kernel<<<dim3(HW / 128, BATCH), 128>>>(x1, x2, xb0, out);
    ef_kernel<<<dim3(NDS / 128, BATCH), 128>>>(ev, ew0, eb0, ew1, eb1);
    qkv_kernel<<<dim3(NDS / 128, BATCH), 128>>>(out, xw1, xb1, qw, qb, kw, kb, vw, vb);
    attn_kernel<<<dim3(NDS / 128, BATCH), 256, ATTN_SMEM>>>();
    epilogue_kernel<<<(2 * BATCH * CHN * HW / 4) / 256, 256>>>(gamma, out);
}

// round 3
// speedup vs baseline: 3.7456x; 1.4885x over previous
#include <cuda_runtime.h>
#include <cuda_fp16.h>
#include <math.h>

#define BATCH 4
#define CHN 64
#define HW 65536        // 256*256
#define NDS 4096        // 64*64 downsampled pixels
#define THITA_F 1.0e-4f
#define OUT2OFF (BATCH * CHN * HW)

// ---------------- scratch (device globals) ----------------------------------
__device__ float  g_xds[BATCH * CHN * NDS];     // down4(x) fp32 [b][c][n]
__device__ float  g_efd[BATCH * CHN * NDS];     // ef downsampled fp32 [b][c][n]
__device__ __half g_qh[BATCH * NDS * CHN];      // [b][n][d] f16
__device__ __half g_kh[BATCH * NDS * CHN];
__device__ __half g_vh[BATCH * NDS * CHN];
__device__ float  g_O[BATCH * CHN * NDS];       // attention output [b][d][m]

// ============================================================================
// shared small-GEMM helpers (64x64 conv at ds pixels, 4 threads/pixel)
// ============================================================================
__device__ __forceinline__ void gemm64(float* acc, const float* ws,
                                       const float* src, int q, int nn)
{
    #pragma unroll
    for (int c = 0; c < 64; c += 4) {
        float v0 = src[c * 68 + nn],       v1 = src[(c + 1) * 68 + nn];
        float v2 = src[(c + 2) * 68 + nn], v3 = src[(c + 3) * 68 + nn];
        #pragma unroll
        for (int j = 0; j < 16; j++) {
            const float4 w4 = *(const float4*)&ws[(q * 16 + j) * 68 + c];
            acc[j] = fmaf(w4.x, v0, acc[j]);
            acc[j] = fmaf(w4.y, v1, acc[j]);
            acc[j] = fmaf(w4.z, v2, acc[j]);
            acc[j] = fmaf(w4.w, v3, acc[j]);
        }
    }
}
__device__ __forceinline__ void load_ws64(float* ws, const float* w, int t) {
    #pragma unroll
    for (int r = 0; r < 16; r++) {
        int i = r * 256 + t, o = i >> 6, c = i & 63;
        ws[o * 68 + c] = w[i];
    }
}

// ============================================================================
// K1: conv0_ds — x at downsampled pixels only (fp32). 256 thr, 64 px/block.
// ============================================================================
#define C0DS_SMEM (64 * 196 * 4 + 192 * 68 * 4)
__global__ __launch_bounds__(256) void conv0ds_kernel(
    const float* __restrict__ x1, const float* __restrict__ x2,
    const float* __restrict__ w,  const float* __restrict__ bias)
{
    extern __shared__ float sm[];
    float* ws = sm;                 // [64][196]
    float* as = sm + 64 * 196;      // [192][68]
    int t = threadIdx.x, q = t >> 6, nn = t & 63;
    int blk = blockIdx.x, b = blockIdx.y;
    int n = (blk << 6) + nn;

    for (int i = t; i < 12288; i += 256) {
        int o = i / 192, c = i - o * 192;
        ws[o * 196 + c] = w[i];
    }
    for (int i = t; i < 12288; i += 256) {
        int c = i >> 6, x = i & 63;
        const float* s = (c < 128) ? x1 + (size_t)(b * 128 + c) * HW
                                   : x2 + (size_t)(b * 64 + c - 128) * HW;
        as[c * 68 + x] = s[(blk << 10) + (x << 2)];
    }
    __syncthreads();

    float acc[16];
    #pragma unroll
    for (int j = 0; j < 16; j++) acc[j] = 0.0f;
    #pragma unroll
    for (int c = 0; c < 192; c += 4) {
        float v0 = as[c * 68 + nn],       v1 = as[(c + 1) * 68 + nn];
        float v2 = as[(c + 2) * 68 + nn], v3 = as[(c + 3) * 68 + nn];
        #pragma unroll
        for (int j = 0; j < 16; j++) {
            const float4 w4 = *(const float4*)&ws[(q * 16 + j) * 196 + c];
            acc[j] = fmaf(w4.x, v0, acc[j]);
            acc[j] = fmaf(w4.y, v1, acc[j]);
            acc[j] = fmaf(w4.z, v2, acc[j]);
            acc[j] = fmaf(w4.w, v3, acc[j]);
        }
    }
    #pragma unroll
    for (int j = 0; j < 16; j++) {
        int o = q * 16 + j;
        g_xds[(size_t)(b * 64 + o) * NDS + n] =
            fmaxf(acc[j] + __ldg(&bias[o]), 0.0f);
    }
}

// ============================================================================
// K2: ef path at ds pixels (fp32): two chained 64x64 convs.
// ============================================================================
#define EF_SMEM (3 * 64 * 68 * 4)
__global__ __launch_bounds__(256) void ef_kernel(
    const float* __restrict__ event,
    const float* __restrict__ w0, const float* __restrict__ b0,
    const float* __restrict__ w1, const float* __restrict__ b1)
{
    extern __shared__ float sm[];
    float* ws = sm;
    float* ts = sm + 64 * 68;
    float* ae = sm + 2 * 64 * 68;
    int t = threadIdx.x, q = t >> 6, nn = t & 63;
    int blk = blockIdx.x, b = blockIdx.y;
    int n = (blk << 6) + nn;

    load_ws64(ws, w0, t);
    for (int i = t; i < 4096; i += 256) {
        int c = i >> 6, x = i & 63;
        ae[c * 68 + x] = event[(size_t)(b * 64 + c) * HW + (blk << 10) + (x << 2)];
    }
    __syncthreads();

    float acc[16];
    #pragma unroll
    for (int j = 0; j < 16; j++) acc[j] = 0.0f;
    gemm64(acc, ws, ae, q, nn);
    #pragma unroll
    for (int j = 0; j < 16; j++)
        ts[(q * 16 + j) * 68 + nn] = fmaxf(acc[j] + __ldg(&b0[q * 16 + j]), 0.0f);
    __syncthreads();
    load_ws64(ws, w1, t);
    __syncthreads();

    #pragma unroll
    for (int j = 0; j < 16; j++) acc[j] = 0.0f;
    gemm64(acc, ws, ts, q, nn);
    #pragma unroll
    for (int j = 0; j < 16; j++) {
        int o = q * 16 + j;
        g_efd[(size_t)(b * 64 + o) * NDS + n] =
            fmaxf(acc[j] + __ldg(&b1[o]), 0.0f);
    }
}

// ============================================================================
// K3: qkv — t = relu(xw1@x_ds), q/v from t, k from ef_d. f16 [b][n][d] out.
// ============================================================================
#define QKV_SMEM (3 * 64 * 68 * 4)
__device__ __forceinline__ unsigned hpack(__half a, __half b) {
    __half2 h = __halves2half2(a, b);
    return *(unsigned*)&h;
}
__device__ __forceinline__ void store16h(__half* dst, const float* acc,
                                         const float* bias, int o0)
{
    unsigned u[8];
    #pragma unroll
    for (int j = 0; j < 8; j++) {
        float r0 = fmaxf(acc[2*j]   + __ldg(&bias[o0 + 2*j]),   0.0f);
        float r1 = fmaxf(acc[2*j+1] + __ldg(&bias[o0 + 2*j+1]), 0.0f);
        u[j] = hpack(__float2half_rn(r0), __float2half_rn(r1));
    }
    ((uint4*)dst)[0] = make_uint4(u[0], u[1], u[2], u[3]);
    ((uint4*)dst)[1] = make_uint4(u[4], u[5], u[6], u[7]);
}

__global__ __launch_bounds__(256) void qkv_kernel(
    const float* __restrict__ xw1, const float* __restrict__ xb1,
    const float* __restrict__ qw,  const float* __restrict__ qb,
    const float* __restrict__ kw,  const float* __restrict__ kb,
    const float* __restrict__ vw,  const float* __restrict__ vb)
{
    extern __shared__ float sm[];
    float* ws = sm;
    float* ts = sm + 64 * 68;
    float* as = sm + 2 * 64 * 68;
    int t = threadIdx.x, q = t >> 6, nn = t & 63;
    int blk = blockIdx.x, b = blockIdx.y;
    int n = (blk << 6) + nn;
    int o0 = q * 16;
    __half* outbase_off = (__half*)0;  (void)outbase_off;

    load_ws64(ws, xw1, t);
    for (int i = t; i < 4096; i += 256) {
        int c = i >> 6, x = i & 63;
        as[c * 68 + x] = g_xds[(size_t)(b * 64 + c) * NDS + (blk << 6) + x];
    }
    __syncthreads();

    float acc[16];
    // t = relu(xw1 @ x_ds + xb1) -> ts
    #pragma unroll
    for (int j = 0; j < 16; j++) acc[j] = 0.0f;
    gemm64(acc, ws, as, q, nn);
    #pragma unroll
    for (int j = 0; j < 16; j++)
        ts[(o0 + j) * 68 + nn] = fmaxf(acc[j] + __ldg(&xb1[o0 + j]), 0.0f);
    __syncthreads();
    load_ws64(ws, qw, t);
    __syncthreads();

    // q
    #pragma unroll
    for (int j = 0; j < 16; j++) acc[j] = 0.0f;
    gemm64(acc, ws, ts, q, nn);
    store16h(g_qh + ((size_t)b * NDS + n) * 64 + o0, acc, qb, o0);
    __syncthreads();
    load_ws64(ws, vw, t);
    __syncthreads();

    // v
    #pragma unroll
    for (int j = 0; j < 16; j++) acc[j] = 0.0f;
    gemm64(acc, ws, ts, q, nn);
    store16h(g_vh + ((size_t)b * NDS + n) * 64 + o0, acc, vb, o0);
    __syncthreads();
    load_ws64(ws, kw, t);
    for (int i = t; i < 4096; i += 256) {
        int c = i >> 6, x = i & 63;
        as[c * 68 + x] = g_efd[(size_t)(b * 64 + c) * NDS + (blk << 6) + x];
    }
    __syncthreads();

    // k
    #pragma unroll
    for (int j = 0; j < 16; j++) acc[j] = 0.0f;
    gemm64(acc, ws, as, q, nn);
    store16h(g_kh + ((size_t)b * NDS + n) * 64 + o0, acc, kb, o0);
}

// ============================================================================
// K4: flash attention, f16 mma (unchanged from round 2)
// ============================================================================
#define SM_STRIDE 72
#define ATTN_SMEM ((128 * SM_STRIDE + 4 * 64 * SM_STRIDE) * 2)

__device__ __forceinline__ void mma16816(float* d,
    unsigned a0, unsigned a1, unsigned a2, unsigned a3,
    unsigned b0, unsigned b1)
{
    asm volatile(
        "mma.sync.aligned.m16n8k16.row.col.f32.f16.f16.f32 "
        "{%0,%1,%2,%3}, {%4,%5,%6,%7}, {%8,%9}, {%0,%1,%2,%3};\n"
        : "+f"(d[0]), "+f"(d[1]), "+f"(d[2]), "+f"(d[3])
        : "r"(a0), "r"(a1), "r"(a2), "r"(a3), "r"(b0), "r"(b1));
}
__device__ __forceinline__ void ldm4(unsigned* r, unsigned a) {
    asm volatile("ldmatrix.sync.aligned.m8n8.x4.shared.b16 {%0,%1,%2,%3}, [%4];\n"
        : "=r"(r[0]), "=r"(r[1]), "=r"(r[2]), "=r"(r[3]) : "r"(a));
}
__device__ __forceinline__ void ldm4t(unsigned* r, unsigned a) {
    asm volatile("ldmatrix.sync.aligned.m8n8.x4.trans.shared.b16 {%0,%1,%2,%3}, [%4];\n"
        : "=r"(r[0]), "=r"(r[1]), "=r"(r[2]), "=r"(r[3]) : "r"(a));
}
__device__ __forceinline__ void cpasync16(unsigned dst, const void* src) {
    asm volatile("cp.async.cg.shared.global [%0], [%1], 16;\n"
        :: "r"(dst), "l"(src));
}
__device__ __forceinline__ float sexp(float s, float c) {
    float t = fmaf(s, 12102203.16f, c);
    t = fmaxf(t, 0.0f);
    return __int_as_float(__float2int_rn(t));
}
__device__ __forceinline__ unsigned packh2(float a, float b) {
    __half2 h = __floats2half2_rn(a, b);
    return *(unsigned*)&h;
}

__global__ __launch_bounds__(256, 1) void attn_kernel()
{
    extern __shared__ __half smh[];
    __half* qs  = smh;
    __half* ks0 = smh + 128 * SM_STRIDE;
    __half* vs0 = ks0 + 2 * 64 * SM_STRIDE;

    int tid  = threadIdx.x;
    int lane = tid & 31, w = tid >> 5;
    int gid  = lane >> 2, tig = lane & 3;
    int b    = blockIdx.y;
    int m0   = blockIdx.x << 7;

    const __half* qg = g_qh + (size_t)b * NDS * 64;
    const __half* kg = g_kh + (size_t)b * NDS * 64;
    const __half* vg = g_vh + (size_t)b * NDS * 64;

    unsigned qs_base = (unsigned)__cvta_generic_to_shared(qs);
    unsigned ks_base = (unsigned)__cvta_generic_to_shared(ks0);
    unsigned vs_base = (unsigned)__cvta_generic_to_shared(vs0);

    #pragma unroll
    for (int rep = 0; rep < 2; rep++) {
        int c = tid + rep * 256;
        int row = c >> 3, off = c & 7;
        cpasync16(ks_base + (row * SM_STRIDE + off * 8) * 2, kg + row * 64 + off * 8);
        cpasync16(vs_base + (row * SM_STRIDE + off * 8) * 2, vg + row * 64 + off * 8);
    }
    asm volatile("cp.async.commit_group;\n");

    for (int c = tid; c < 1024; c += 256) {
        int row = c >> 3, off = c & 7;
        *(uint4*)(qs + row * SM_STRIDE + off * 8) =
            *(const uint4*)(qg + (size_t)(m0 + row) * 64 + off * 8);
    }
    asm volatile("cp.async.wait_group 0;\n");
    __syncthreads();

    unsigned qa[4][4];
    {
        int row = (w << 4) + (lane & 15);
        #pragma unroll
        for (int kc = 0; kc < 4; kc++) {
            int dof = kc * 16 + (lane >> 4) * 8;
            ldm4(qa[kc], qs_base + (row * SM_STRIDE + dof) * 2);
        }
    }

    float Of[8][4];
    #pragma unroll
    for (int dc = 0; dc < 8; dc++)
        #pragma unroll
        for (int q = 0; q < 4; q++) Of[dc][q] = 0.0f;
    float mrow0 = -1e30f, mrow1 = -1e30f, lrow0 = 0.0f, lrow1 = 0.0f;
    const unsigned ONES = 0x3C003C00u;

    for (int it = 0; it < 64; it++) {
        int bf = it & 1;
        unsigned ksb = ks_base + bf * 64 * SM_STRIDE * 2;
        unsigned vsb = vs_base + bf * 64 * SM_STRIDE * 2;

        if (it + 1 < 64) {
            int n0n = (it + 1) << 6;
            int nb  = (it + 1) & 1;
            #pragma unroll
            for (int rep = 0; rep < 2; rep++) {
                int c = tid + rep * 256;
                int row = c >> 3, off = c & 7;
                cpasync16(ks_base + (nb * 64 * SM_STRIDE + row * SM_STRIDE + off * 8) * 2,
                          kg + (size_t)(n0n + row) * 64 + off * 8);
                cpasync16(vs_base + (nb * 64 * SM_STRIDE + row * SM_STRIDE + off * 8) * 2,
                          vg + (size_t)(n0n + row) * 64 + off * 8);
            }
            asm volatile("cp.async.commit_group;\n");
        }

        float S[8][4];
        #pragma unroll
        for (int nc = 0; nc < 8; nc++) {
            unsigned kb[8];
            int krow = nc * 8 + (lane & 7);
            int kd   = (lane >> 3) * 8;
            ldm4(kb,     ksb + (krow * SM_STRIDE + kd) * 2);
            ldm4(kb + 4, ksb + (krow * SM_STRIDE + 32 + kd) * 2);
            #pragma unroll
            for (int q = 0; q < 4; q++) S[nc][q] = 0.0f;
            mma16816(S[nc], qa[0][0], qa[0][1], qa[0][2], qa[0][3], kb[0], kb[1]);
            mma16816(S[nc], qa[1][0], qa[1][1], qa[1][2], qa[1][3], kb[2], kb[3]);
            mma16816(S[nc], qa[2][0], qa[2][1], qa[2][2], qa[2][3], kb[4], kb[5]);
            mma16816(S[nc], qa[3][0], qa[3][1], qa[3][2], qa[3][3], kb[6], kb[7]);
        }

        float tm0 = fmaxf(S[0][0], S[0][1]);
        float tm1 = fmaxf(S[0][2], S[0][3]);
        #pragma unroll
        for (int nc = 1; nc < 8; nc++) {
            tm0 = fmaxf(tm0, fmaxf(S[nc][0], S[nc][1]));
            tm1 = fmaxf(tm1, fmaxf(S[nc][2], S[nc][3]));
        }
        tm0 = fmaxf(tm0, __shfl_xor_sync(0xffffffffu, tm0, 1));
        tm0 = fmaxf(tm0, __shfl_xor_sync(0xffffffffu, tm0, 2));
        tm1 = fmaxf(tm1, __shfl_xor_sync(0xffffffffu, tm1, 1));
        tm1 = fmaxf(tm1, __shfl_xor_sync(0xffffffffu, tm1, 2));
        float nm0 = fmaxf(mrow0, tm0), nm1 = fmaxf(mrow1, tm1);
        float sc0 = exp2f((mrow0 - nm0) * 1.44269504f);
        float sc1 = exp2f((mrow1 - nm1) * 1.44269504f);
        mrow0 = nm0; mrow1 = nm1;
        float c0 = 1064866805.0f - nm0 * 12102203.16f;
        float c1 = 1064866805.0f - nm1 * 12102203.16f;

        unsigned P[4][4];
        #pragma unroll
        for (int jc = 0; jc < 4; jc++) {
            P[jc][0] = packh2(sexp(S[2*jc][0],   c0), sexp(S[2*jc][1],   c0));
            P[jc][1] = packh2(sexp(S[2*jc][2],   c1), sexp(S[2*jc][3],   c1));
            P[jc][2] = packh2(sexp(S[2*jc+1][0], c0), sexp(S[2*jc+1][1], c0));
            P[jc][3] = packh2(sexp(S[2*jc+1][2], c1), sexp(S[2*jc+1][3], c1));
        }

        float lf[4] = {0.0f, 0.0f, 0.0f, 0.0f};
        #pragma unroll
        for (int jc = 0; jc < 4; jc++)
            mma16816(lf, P[jc][0], P[jc][1], P[jc][2], P[jc][3], ONES, ONES);
        lrow0 = lrow0 * sc0 + lf[0];
        lrow1 = lrow1 * sc1 + lf[2];

        #pragma unroll
        for (int dc = 0; dc < 8; dc++) {
            Of[dc][0] *= sc0; Of[dc][1] *= sc0;
            Of[dc][2] *= sc1; Of[dc][3] *= sc1;
        }

        #pragma unroll
        for (int jc = 0; jc < 4; jc++) {
            int vrow = jc * 16 + (lane & 15);
            int vcb  = (lane >> 4) * 8;
            #pragma unroll
            for (int dcp = 0; dcp < 4; dcp++) {
                unsigned vb[4];
                ldm4t(vb, vsb + (vrow * SM_STRIDE + dcp * 16 + vcb) * 2);
                mma16816(Of[2*dcp],     P[jc][0], P[jc][1], P[jc][2], P[jc][3], vb[0], vb[1]);
                mma16816(Of[2*dcp + 1], P[jc][0], P[jc][1], P[jc][2], P[jc][3], vb[2], vb[3]);
            }
        }

        if (it + 1 < 64) {
            asm volatile("cp.async.wait_group 0;\n");
            __syncthreads();
        }
    }

    float inv0 = 1.0f / lrow0, inv1 = 1.0f / lrow1;
    int m = m0 + (w << 4) + gid;
    #pragma unroll
    for (int dc = 0; dc < 8; dc++) {
        int d0 = dc * 8 + tig * 2;
        g_O[(b * 64 + d0)     * NDS + m]     = Of[dc][0] * inv0;
        g_O[(b * 64 + d0 + 1) * NDS + m]     = Of[dc][1] * inv0;
        g_O[(b * 64 + d0)     * NDS + m + 8] = Of[dc][2] * inv1;
        g_O[(b * 64 + d0 + 1) * NDS + m + 8] = Of[dc][3] * inv1;
    }
}

// ============================================================================
// K5: convout — full-res conv0 on tensor cores (f16 hi/lo 3-pass) fused with
// out = relu(conv+bias) + tg*up4(O), plus ef_up = up4(ef_d).
// Block: 256 threads (8 warps), one image row (256 px). Grid (256, BATCH).
// smem: wh/wl [64][200] f16; act hi/lo double-buffered [16][264] f16;
//       epilogue overlays osm/esm [64][68] f32 on the act region.
// ============================================================================
#define CO_OFF_WH  0
#define CO_OFF_WL  25600
#define CO_OFF_ACT 51200
#define CO_ACT_BUF 16896                 // hi[16][264] + lo[16][264] per buffer
#define CONVOUT_SMEM (51200 + 2 * 17408) // weights + epilogue overlay (34816 > 2*16896)

__global__ __launch_bounds__(256, 2) void convout_kernel(
    const float* __restrict__ x1, const float* __restrict__ x2,
    const float* __restrict__ w,  const float* __restrict__ bias,
    const float* __restrict__ gamma, float* __restrict__ out)
{
    extern __shared__ char smc[];
    __half* WH = (__half*)(smc + CO_OFF_WH);
    __half* WL = (__half*)(smc + CO_OFF_WL);
    unsigned smu = (unsigned)__cvta_generic_to_shared(smc);

    int t = threadIdx.x;
    int lane = t & 31, wp = t >> 5;
    int ln15 = lane & 15, hb8 = (lane >> 4) * 8;
    int y = blockIdx.x, b = blockIdx.y;
    int p0 = y << 8;
    int ndbase = (y >> 2) << 6;

    // weights -> f16 hi/lo in smem
    for (int i = t; i < 12288; i += 256) {
        int o = i / 192, c = i - o * 192;
        float v = w[i];
        __half h = __float2half_rn(v);
        WH[o * 200 + c] = h;
        WL[o * 200 + c] = __float2half_rn(v - __half2float(h));
    }

    int r = t >> 4, col0 = (t & 15) << 4;
    // stage kstep 0
    float f[16];
    {
        const float* s = x1 + (size_t)(b * 128 + r) * HW + p0 + col0;  // ks=0: c=r<128
        #pragma unroll
        for (int j = 0; j < 4; j++) *(float4*)&f[4*j] = *(const float4*)(s + 4*j);
        unsigned H[8], L[8];
        #pragma unroll
        for (int j = 0; j < 8; j++) {
            __half h0 = __float2half_rn(f[2*j]), h1 = __float2half_rn(f[2*j+1]);
            H[j] = hpack(h0, h1);
            L[j] = hpack(__float2half_rn(f[2*j]   - __half2float(h0)),
                         __float2half_rn(f[2*j+1] - __half2float(h1)));
        }
        __half* AH = (__half*)(smc + CO_OFF_ACT);
        __half* AL = AH + 4224;
        *(uint4*)&AH[r * 264 + col0]     = make_uint4(H[0], H[1], H[2], H[3]);
        *(uint4*)&AH[r * 264 + col0 + 8] = make_uint4(H[4], H[5], H[6], H[7]);
        *(uint4*)&AL[r * 264 + col0]     = make_uint4(L[0], L[1], L[2], L[3]);
        *(uint4*)&AL[r * 264 + col0 + 8] = make_uint4(L[4], L[5], L[6], L[7]);
    }
    __syncthreads();

    float acc[4][4][4];
    #pragma unroll
    for (int mt = 0; mt < 4; mt++)
        #pragma unroll
        for (int nb = 0; nb < 4; nb++)
            #pragma unroll
            for (int q = 0; q < 4; q++) acc[mt][nb][q] = 0.0f;

    unsigned whB = smu + CO_OFF_WH + (ln15 * 200 + hb8) * 2;
    unsigned wlB = smu + CO_OFF_WL + (ln15 * 200 + hb8) * 2;

    #pragma unroll 1
    for (int ks = 0; ks < 12; ks++) {
        // prefetch next kstep activations
        if (ks < 11) {
            int c = (ks + 1) * 16 + r;
            const float* s = (c < 128) ? x1 + (size_t)(b * 128 + c) * HW
                                       : x2 + (size_t)(b * 64 + c - 128) * HW;
            s += p0 + col0;
            #pragma unroll
            for (int j = 0; j < 4; j++) *(float4*)&f[4*j] = *(const float4*)(s + 4*j);
        }

        int bf = ks & 1;
        unsigned actH = smu + CO_OFF_ACT + bf * CO_ACT_BUF +
                        (ln15 * 264 + wp * 32 + hb8) * 2;
        unsigned actL = actH + 4224 * 2;

        unsigned A[4][4], Bh[8], Bl[8];
        ldm4t(Bh,     actH);
        ldm4t(Bh + 4, actH + 32);
        ldm4t(Bl,     actL);
        ldm4t(Bl + 4, actL + 32);
        #pragma unroll
        for (int mt = 0; mt < 4; mt++)
            ldm4(A[mt], whB + mt * 6400 + ks * 32);
        #pragma unroll
        for (int mt = 0; mt < 4; mt++) {
            mma16816(acc[mt][0], A[mt][0], A[mt][1], A[mt][2], A[mt][3], Bh[0], Bh[1]);
            mma16816(acc[mt][1], A[mt][0], A[mt][1], A[mt][2], A[mt][3], Bh[2], Bh[3]);
            mma16816(acc[mt][2], A[mt][0], A[mt][1], A[mt][2], A[mt][3], Bh[4], Bh[5]);
            mma16816(acc[mt][3], A[mt][0], A[mt][1], A[mt][2], A[mt][3], Bh[6], Bh[7]);
            mma16816(acc[mt][0], A[mt][0], A[mt][1], A[mt][2], A[mt][3], Bl[0], Bl[1]);
            mma16816(acc[mt][1], A[mt][0], A[mt][1], A[mt][2], A[mt][3], Bl[2], Bl[3]);
            mma16816(acc[mt][2], A[mt][0], A[mt][1], A[mt][2], A[mt][3], Bl[4], Bl[5]);
            mma16816(acc[mt][3], A[mt][0], A[mt][1], A[mt][2], A[mt][3], Bl[6], Bl[7]);
        }
        #pragma unroll
        for (int mt = 0; mt < 4; mt++)
            ldm4(A[mt], wlB + mt * 6400 + ks * 32);
        #pragma unroll
        for (int mt = 0; mt < 4; mt++) {
            mma16816(acc[mt][0], A[mt][0], A[mt][1], A[mt][2], A[mt][3], Bh[0], Bh[1]);
            mma16816(acc[mt][1], A[mt][0], A[mt][1], A[mt][2], A[mt][3], Bh[2], Bh[3]);
            mma16816(acc[mt][2], A[mt][0], A[mt][1], A[mt][2], A[mt][3], Bh[4], Bh[5]);
            mma16816(acc[mt][3], A[mt][0], A[mt][1], A[mt][2], A[mt][3], Bh[6], Bh[7]);
        }

        if (ks < 11) {
            unsigned H[8], L[8];
            #pragma unroll
            for (int j = 0; j < 8; j++) {
                __half h0 = __float2half_rn(f[2*j]), h1 = __float2half_rn(f[2*j+1]);
                H[j] = hpack(h0, h1);
                L[j] = hpack(__float2half_rn(f[2*j]   - __half2float(h0)),
                             __float2half_rn(f[2*j+1] - __half2float(h1)));
            }
            __half* AH = (__half*)(smc + CO_OFF_ACT + (bf ^ 1) * CO_ACT_BUF);
            __half* AL = AH + 4224;
            *(uint4*)&AH[r * 264 + col0]     = make_uint4(H[0], H[1], H[2], H[3]);
            *(uint4*)&AH[r * 264 + col0 + 8] = make_uint4(H[4], H[5], H[6], H[7]);
            *(uint4*)&AL[r * 264 + col0]     = make_uint4(L[0], L[1], L[2], L[3]);
            *(uint4*)&AL[r * 264 + col0 + 8] = make_uint4(L[4], L[5], L[6], L[7]);
            __syncthreads();
        }
    }
    __syncthreads();

    // epilogue overlay: OS/ES [64][68] f32
    float* OS = (float*)(smc + CO_OFF_ACT);
    float* ES = OS + 64 * 68;
    {
        int o = t >> 2, c0 = (t & 3) << 4;
        const float* po = g_O   + (size_t)(b * 64 + o) * NDS + ndbase + c0;
        const float* pe = g_efd + (size_t)(b * 64 + o) * NDS + ndbase + c0;
        #pragma unroll
        for (int j = 0; j < 4; j++) {
            *(float4*)&OS[o * 68 + c0 + 4*j] = *(const float4*)(po + 4*j);
            *(float4*)&ES[o * 68 + c0 + 4*j] = *(const float4*)(pe + 4*j);
        }
    }
    __syncthreads();

    float tg = THITA_F * __ldg(gamma);
    int g = lane >> 2, tig = lane & 3;
    #pragma unroll
    for (int mt = 0; mt < 4; mt++) {
        int o = mt * 16 + g;
        float bb0 = __ldg(&bias[o]), bb1 = __ldg(&bias[o + 8]);
        #pragma unroll
        for (int nb = 0; nb < 4; nb++) {
            int px = wp * 32 + nb * 8 + tig * 2;
            int ndc = px >> 2;
            float a0 = tg * OS[o * 68 + ndc];
            float a1 = tg * OS[(o + 8) * 68 + ndc];
            float2 r0 = make_float2(fmaxf(acc[mt][nb][0] + bb0, 0.0f) + a0,
                                    fmaxf(acc[mt][nb][1] + bb0, 0.0f) + a0);
            float2 r1 = make_float2(fmaxf(acc[mt][nb][2] + bb1, 0.0f) + a1,
                                    fmaxf(acc[mt][nb][3] + bb1, 0.0f) + a1);
            *(float2*)(out + (size_t)(b * 64 + o)     * HW + p0 + px) = r0;
            *(float2*)(out + (size_t)(b * 64 + o + 8) * HW + p0 + px) = r1;
        }
    }

    // ef_up
    int xq = t & 63;
    #pragma unroll
    for (int rep = 0; rep < 16; rep++) {
        int o = rep * 4 + (t >> 6);
        float v = ES[o * 68 + xq];
        *(float4*)(out + OUT2OFF + (size_t)(b * 64 + o) * HW + p0 + (xq << 2)) =
            make_float4(v, v, v, v);
    }
}

// ============================================================================
extern "C" void kernel_launch(void* const* d_in, const int* in_sizes, int n_in,
                              void* d_out, int out_size)
{
    const float* x1    = (const float*)d_in[0];
    const float* x2    = (const float*)d_in[1];
    const float* ev    = (const float*)d_in[2];
    const float* xw0   = (const float*)d_in[3];
    const float* xb0   = (const float*)d_in[4];
    const float* xw1   = (const float*)d_in[5];
    const float* xb1   = (const float*)d_in[6];
    const float* ew0   = (const float*)d_in[7];
    const float* eb0   = (const float*)d_in[8];
    const float* ew1   = (const float*)d_in[9];
    const float* eb1   = (const float*)d_in[10];
    const float* qw    = (const float*)d_in[11];
    const float* qb    = (const float*)d_in[12];
    const float* kw    = (const float*)d_in[13];
    const float* kb    = (const float*)d_in[14];
    const float* vw    = (const float*)d_in[15];
    const float* vb    = (const float*)d_in[16];
    const float* gamma = (const float*)d_in[17];
    float* out = (float*)d_out;

    cudaFuncSetAttribute(conv0ds_kernel,
                         cudaFuncAttributeMaxDynamicSharedMemorySize, C0DS_SMEM);
    cudaFuncSetAttribute(ef_kernel,
                         cudaFuncAttributeMaxDynamicSharedMemorySize, EF_SMEM);
    cudaFuncSetAttribute(qkv_kernel,
                         cudaFuncAttributeMaxDynamicSharedMemorySize, QKV_SMEM);
    cudaFuncSetAttribute(attn_kernel,
                         cudaFuncAttributeMaxDynamicSharedMemorySize, ATTN_SMEM);
    cudaFuncSetAttribute(convout_kernel,
                         cudaFuncAttributeMaxDynamicSharedMemorySize, CONVOUT_SMEM);

    conv0ds_kernel<<<dim3(NDS / 64, BATCH), 256, C0DS_SMEM>>>(x1, x2, xw0, xb0);
    ef_kernel<<<dim3(NDS / 64, BATCH), 256, EF_SMEM>>>(ev, ew0, eb0, ew1, eb1);
    qkv_kernel<<<dim3(NDS / 64, BATCH), 256, QKV_SMEM>>>(xw1, xb1, qw, qb, kw, kb, vw, vb);
    attn_kernel<<<dim3(NDS / 128, BATCH), 256, ATTN_SMEM>>>();
    convout_kernel<<<dim3(256, BATCH), 256, CONVOUT_SMEM>>>(x1, x2, xw0, xb0, gamma, out);
}